// round 1
// baseline (speedup 1.0000x reference)
#include <cuda_runtime.h>
#include <cuda_bf16.h>

// ImageAverage: x [N, 64] f32, image_id [N] i32 SORTED ascending in [0, n_images).
// Output (f32 concat): averaged [n_images, 64], image_id as float [N], counts [n_images].
//
// Strategy: ids sorted -> contiguous segments. One CTA per image:
//   binary-search boundaries, stream contiguous rows with float4 loads,
//   shared-mem tree reduce over 16 row-lanes, divide by count, store.
// No atomics, no scratch, single wave of 1024 CTAs.

__device__ __forceinline__ int lower_bound_dev(const int* __restrict__ ids, int n, int val) {
    int lo = 0, hi = n;
    while (lo < hi) {
        int mid = (lo + hi) >> 1;
        if (ids[mid] < val) lo = mid + 1; else hi = mid;
    }
    return lo;
}

__global__ __launch_bounds__(256) void image_avg_kernel(
    const float* __restrict__ x,
    const int* __restrict__ ids,
    float* __restrict__ out_avg,     // [n_images, 64]
    float* __restrict__ out_counts,  // [n_images]
    int n)
{
    const int img = blockIdx.x;
    // All threads do the same binary search (broadcast loads, L2-resident).
    const int start = lower_bound_dev(ids, n, img);
    const int end   = lower_bound_dev(ids, n, img + 1);
    const int count = end - start;

    const int tid = threadIdx.x;
    const int col = tid & 15;   // which float4 of the 64-dim row (16 per row)
    const int rl  = tid >> 4;   // row lane 0..15

    const float4* __restrict__ xv = reinterpret_cast<const float4*>(x);

    float4 acc = make_float4(0.f, 0.f, 0.f, 0.f);
    for (int r = start + rl; r < end; r += 16) {
        float4 v = __ldg(&xv[(size_t)r * 16 + col]);
        acc.x += v.x; acc.y += v.y; acc.z += v.z; acc.w += v.w;
    }

    __shared__ float4 sh[256];
    sh[tid] = acc;
    __syncthreads();

    // Tree-reduce across row lanes (stride multiples of 16 keep col aligned).
    #pragma unroll
    for (int s = 128; s >= 16; s >>= 1) {
        if (tid < s) {
            float4 a = sh[tid], b = sh[tid + s];
            a.x += b.x; a.y += b.y; a.z += b.z; a.w += b.w;
            sh[tid] = a;
        }
        __syncthreads();
    }

    if (tid < 16) {
        float inv = 1.0f / (float)(count > 0 ? count : 1);
        float4 v = sh[tid];
        v.x *= inv; v.y *= inv; v.z *= inv; v.w *= inv;
        reinterpret_cast<float4*>(out_avg)[(size_t)img * 16 + tid] = v;
    }
    if (tid == 0) {
        out_counts[img] = (float)count;
    }
}

__global__ __launch_bounds__(256) void copy_ids_kernel(
    const int* __restrict__ ids,
    float* __restrict__ out,
    int n4)  // n / 4
{
    int i = blockIdx.x * blockDim.x + threadIdx.x;
    if (i < n4) {
        int4 v = reinterpret_cast<const int4*>(ids)[i];
        float4 f = make_float4((float)v.x, (float)v.y, (float)v.z, (float)v.w);
        reinterpret_cast<float4*>(out)[i] = f;
    }
}

extern "C" void kernel_launch(void* const* d_in, const int* in_sizes, int n_in,
                              void* d_out, int out_size) {
    const float* x   = (const float*)d_in[0];
    const int*   ids = (const int*)d_in[1];

    const int n = in_sizes[1];                 // number of rows / reflections
    // out_size = n_images*64 (avg) + n (ids) + n_images (counts)
    const int n_images = (out_size - n) / 65;

    float* out_avg    = (float*)d_out;
    float* out_ids    = out_avg + (size_t)n_images * 64;
    float* out_counts = out_ids + (size_t)n;

    image_avg_kernel<<<n_images, 256>>>(x, ids, out_avg, out_counts, n);

    const int n4 = n / 4;
    const int blocks = (n4 + 255) / 256;
    copy_ids_kernel<<<blocks, 256>>>(ids, out_ids, n4);
}

// round 2
// speedup vs baseline: 1.0175x; 1.0175x over previous
#include <cuda_runtime.h>
#include <cuda_bf16.h>

// ImageAverage: x [N, 64] f32, image_id [N] i32 SORTED ascending in [0, n_images).
// Output (f32 concat): averaged [n_images, 64], image_id as float [N], counts [n_images].
//
// Single fused kernel, one CTA per image:
//   phase 1: copy a uniform int4-aligned chunk of image_id -> float (fused,
//            overlaps with the BW-bound streaming phase of other CTAs)
//   phase 2: binary-search segment boundaries (L2-resident after first CTAs),
//            stream contiguous rows with evict-first float4 loads,
//            smem tree reduce over 16 row-lanes, divide, store.
// No atomics, no scratch, single wave of 1024 CTAs.

__device__ __forceinline__ int lower_bound_dev(const int* __restrict__ ids, int n, int val) {
    int lo = 0, hi = n;
    while (lo < hi) {
        int mid = (lo + hi) >> 1;
        if (__ldg(&ids[mid]) < val) lo = mid + 1; else hi = mid;
    }
    return lo;
}

__global__ __launch_bounds__(256) void image_avg_fused_kernel(
    const float* __restrict__ x,
    const int* __restrict__ ids,
    float* __restrict__ out_avg,     // [n_images, 64]
    float* __restrict__ out_ids,     // [n] (float copy of ids)
    float* __restrict__ out_counts,  // [n_images]
    int n)
{
    const int tid = threadIdx.x;
    const int img = blockIdx.x;

    // ---- Phase 1: fused id copy (uniform chunks, int4/float4 aligned) ----
    {
        const int n4 = n >> 2;
        const int per = (n4 + gridDim.x - 1) / gridDim.x;
        const int base = img * per;
        const int lim = min(base + per, n4);
        const int4* __restrict__ iv = reinterpret_cast<const int4*>(ids);
        float4* __restrict__ ov = reinterpret_cast<float4*>(out_ids);
        for (int i = base + tid; i < lim; i += 256) {
            int4 v = __ldcs(&iv[i]);
            ov[i] = make_float4((float)v.x, (float)v.y, (float)v.z, (float)v.w);
        }
    }

    // ---- Phase 2: segment average ----
    const int start = lower_bound_dev(ids, n, img);
    const int end   = lower_bound_dev(ids, n, img + 1);
    const int count = end - start;

    const int col = tid & 15;   // which float4 of the 64-dim row (16 per row)
    const int rl  = tid >> 4;   // row lane 0..15

    const float4* __restrict__ xv = reinterpret_cast<const float4*>(x);

    float4 acc = make_float4(0.f, 0.f, 0.f, 0.f);
    #pragma unroll 4
    for (int r = start + rl; r < end; r += 16) {
        float4 v = __ldcs(&xv[(size_t)r * 16 + col]);
        acc.x += v.x; acc.y += v.y; acc.z += v.z; acc.w += v.w;
    }

    __shared__ float4 sh[256];
    sh[tid] = acc;
    __syncthreads();

    // Tree-reduce across row lanes (stride multiples of 16 keep col aligned).
    #pragma unroll
    for (int s = 128; s >= 16; s >>= 1) {
        if (tid < s) {
            float4 a = sh[tid], b = sh[tid + s];
            a.x += b.x; a.y += b.y; a.z += b.z; a.w += b.w;
            sh[tid] = a;
        }
        __syncthreads();
    }

    if (tid < 16) {
        float inv = 1.0f / (float)(count > 0 ? count : 1);
        float4 v = sh[tid];
        v.x *= inv; v.y *= inv; v.z *= inv; v.w *= inv;
        reinterpret_cast<float4*>(out_avg)[(size_t)img * 16 + tid] = v;
    }
    if (tid == 0) {
        out_counts[img] = (float)count;
    }
}

extern "C" void kernel_launch(void* const* d_in, const int* in_sizes, int n_in,
                              void* d_out, int out_size) {
    const float* x   = (const float*)d_in[0];
    const int*   ids = (const int*)d_in[1];

    const int n = in_sizes[1];                 // number of rows / reflections
    // out_size = n_images*64 (avg) + n (ids) + n_images (counts)
    const int n_images = (out_size - n) / 65;

    float* out_avg    = (float*)d_out;
    float* out_ids    = out_avg + (size_t)n_images * 64;
    float* out_counts = out_ids + (size_t)n;

    image_avg_fused_kernel<<<n_images, 256>>>(x, ids, out_avg, out_ids, out_counts, n);
}